// round 4
// baseline (speedup 1.0000x reference)
#include <cuda_runtime.h>
#include <math_constants.h>

// Problem constants (match reference setup_inputs)
#define NUM_STATES 10000
#define BATCH      64
#define SEQLEN     4096
#define TPB        256
#define CHUNKS     (SEQLEN / TPB)   // 16
#define GRID       (BATCH * CHUNKS) // 1024

// Scratch (device globals per harness rules)
__device__ float        g_partials[GRID];
__device__ unsigned int g_counter = 0;

__global__ __launch_bounds__(TPB)
void markov_fused_kernel(const int*   __restrict__ seqs,
                         const int*   __restrict__ lengths,
                         const float* __restrict__ initial,
                         const float* __restrict__ trans,
                         float*       __restrict__ out)
{
    const int b     = blockIdx.x >> 4;        // sequence id (16 chunks per sequence)
    const int chunk = blockIdx.x & 15;
    const int tid   = threadIdx.x;
    const int t     = chunk * TPB + tid + 1;  // transition target index, 1..4096
    const int len   = lengths[b];
    const int* s    = seqs + b * SEQLEN;

    // Predicated gather: skip the DRAM line fetch entirely for invalid t.
    // t < len (len <= 4096) implies t <= 4095, so s[t] is in range.
    float v = 0.0f;
    if (t < len) {
        const int sp = s[t - 1];
        const int sc = s[t];
        const float p = __ldg(&trans[(size_t)sp * NUM_STATES + sc]);
        v = __logf(p);
    }

    // ---- block reduction (warp shuffle + shared) ----
    #pragma unroll
    for (int off = 16; off > 0; off >>= 1)
        v += __shfl_down_sync(0xffffffff, v, off);

    __shared__ float warp_sums[TPB / 32];
    const int lane = tid & 31;
    const int wid  = tid >> 5;
    if (lane == 0) warp_sums[wid] = v;
    __syncthreads();

    if (wid == 0) {
        v = (lane < TPB / 32) ? warp_sums[lane] : 0.0f;
        #pragma unroll
        for (int off = 4; off > 0; off >>= 1)
            v += __shfl_down_sync(0xffffffff, v, off);
        if (lane == 0)
            g_partials[blockIdx.x] = v;   // seq b's partials at [16b .. 16b+15]
    }

    // ---- last-block-done finalize (single launch, deterministic) ----
    __shared__ bool isLast;
    if (tid == 0) {
        __threadfence();
        const unsigned int done = atomicAdd(&g_counter, 1u);
        isLast = (done == GRID - 1);
    }
    __syncthreads();
    if (!isLast) return;

    float ll = 0.0f;
    if (tid < BATCH) {
        ll = __logf(__ldg(&initial[__ldg(&seqs[tid * SEQLEN])]));
        #pragma unroll
        for (int c = 0; c < CHUNKS; c++)
            ll += g_partials[tid * CHUNKS + c];
    }

    __shared__ float sll[BATCH];
    if (tid < BATCH) sll[tid] = ll;
    __syncthreads();

    if (tid == 0) {
        float m = -CUDART_INF_F;
        #pragma unroll 8
        for (int i = 0; i < BATCH; i++)
            m = fmaxf(m, sll[i]);
        float ssum = 0.0f;
        #pragma unroll 8
        for (int i = 0; i < BATCH; i++)
            ssum += __expf(sll[i] - m);
        out[0] = -(m + __logf(ssum));
        g_counter = 0;   // reset for next graph replay (determinism)
    }
}

extern "C" void kernel_launch(void* const* d_in, const int* in_sizes, int n_in,
                              void* d_out, int out_size)
{
    const int*   seqs    = (const int*)d_in[0];
    const int*   lengths = (const int*)d_in[1];
    const float* initial = (const float*)d_in[2];
    const float* trans   = (const float*)d_in[3];
    float*       out     = (float*)d_out;

    markov_fused_kernel<<<GRID, TPB>>>(seqs, lengths, initial, trans, out);
}

// round 5
// speedup vs baseline: 1.0175x; 1.0175x over previous
#include <cuda_runtime.h>
#include <math_constants.h>

// Problem constants (match reference setup_inputs)
#define NUM_STATES 10000
#define BATCH      64
#define SEQLEN     4096
#define TPB        128
#define TPT        4                          // transitions per thread
#define BLOCKS_PER_SEQ (SEQLEN / (TPB * TPT)) // 8
#define GRID       (BATCH * BLOCKS_PER_SEQ)   // 512

// Scratch (device globals per harness rules)
__device__ float        g_partials[GRID];
__device__ unsigned int g_counter = 0;

__global__ __launch_bounds__(TPB)
void markov_fused_kernel(const int*   __restrict__ seqs,
                         const int*   __restrict__ lengths,
                         const float* __restrict__ initial,
                         const float* __restrict__ trans,
                         float*       __restrict__ out)
{
    const int b    = blockIdx.x >> 3;          // sequence id (8 blocks per seq)
    const int blk  = blockIdx.x & 7;
    const int tid  = threadIdx.x;
    const int k    = blk * TPB + tid;          // 0..1023 within sequence
    const int base = 4 * k;                    // aligned prev-state base index
    const int len  = lengths[b];
    const int* s   = seqs + b * SEQLEN;

    // states s[base..base+3] aligned int4, s[base+4] guarded edge read
    const int4 pv = *reinterpret_cast<const int4*>(s + base);
    const int  p4 = (base + 4 < SEQLEN) ? s[base + 4] : 0;

    float v = 0.0f;
    if (base + 4 < len) {
        // Hot path (~75% of threads): all 4 transitions valid.
        // 4 independent uncached gathers issued back-to-back (MLP=4).
        const float r0 = __ldcv(&trans[(size_t)pv.x * NUM_STATES + pv.y]);
        const float r1 = __ldcv(&trans[(size_t)pv.y * NUM_STATES + pv.z]);
        const float r2 = __ldcv(&trans[(size_t)pv.z * NUM_STATES + pv.w]);
        const float r3 = __ldcv(&trans[(size_t)pv.w * NUM_STATES + p4]);
        v = (__logf(r0) + __logf(r1)) + (__logf(r2) + __logf(r3));
    } else if (base + 1 < len) {
        // Boundary thread: per-element predicated gathers.
        const int p[5] = {pv.x, pv.y, pv.z, pv.w, p4};
        #pragma unroll
        for (int j = 0; j < TPT; j++) {
            if (base + 1 + j < len)
                v += __logf(__ldcv(&trans[(size_t)p[j] * NUM_STATES + p[j + 1]]));
        }
    }
    // else: entirely past the valid range — no loads at all.

    // ---- block reduction (warp shuffle + shared) ----
    #pragma unroll
    for (int off = 16; off > 0; off >>= 1)
        v += __shfl_down_sync(0xffffffff, v, off);

    __shared__ float warp_sums[TPB / 32];
    const int lane = tid & 31;
    const int wid  = tid >> 5;
    if (lane == 0) warp_sums[wid] = v;
    __syncthreads();

    if (wid == 0) {
        v = (lane < TPB / 32) ? warp_sums[lane] : 0.0f;
        #pragma unroll
        for (int off = 2; off > 0; off >>= 1)
            v += __shfl_down_sync(0xffffffff, v, off);
        if (lane == 0)
            g_partials[blockIdx.x] = v;   // seq b's partials at [8b .. 8b+7]
    }

    // ---- last-block-done finalize (single launch, deterministic) ----
    __shared__ bool isLast;
    if (tid == 0) {
        __threadfence();
        const unsigned int done = atomicAdd(&g_counter, 1u);
        isLast = (done == GRID - 1);
    }
    __syncthreads();
    if (!isLast) return;

    float ll = 0.0f;
    if (tid < BATCH) {
        ll = __logf(__ldg(&initial[__ldg(&seqs[tid * SEQLEN])]));
        #pragma unroll
        for (int c = 0; c < BLOCKS_PER_SEQ; c++)
            ll += g_partials[tid * BLOCKS_PER_SEQ + c];
    }

    __shared__ float sll[BATCH];
    if (tid < BATCH) sll[tid] = ll;
    __syncthreads();

    if (tid == 0) {
        float m = -CUDART_INF_F;
        #pragma unroll 8
        for (int i = 0; i < BATCH; i++)
            m = fmaxf(m, sll[i]);
        float ssum = 0.0f;
        #pragma unroll 8
        for (int i = 0; i < BATCH; i++)
            ssum += __expf(sll[i] - m);
        out[0] = -(m + __logf(ssum));
        g_counter = 0;   // reset for next graph replay (determinism)
    }
}

extern "C" void kernel_launch(void* const* d_in, const int* in_sizes, int n_in,
                              void* d_out, int out_size)
{
    const int*   seqs    = (const int*)d_in[0];
    const int*   lengths = (const int*)d_in[1];
    const float* initial = (const float*)d_in[2];
    const float* trans   = (const float*)d_in[3];
    float*       out     = (float*)d_out;

    markov_fused_kernel<<<GRID, TPB>>>(seqs, lengths, initial, trans, out);
}